// round 2
// baseline (speedup 1.0000x reference)
#include <cuda_runtime.h>
#include <cuda_bf16.h>
#include <cstdint>

// ---------------- problem constants ----------------
// BS=256, C=256, H=W=16, HW=256
// feat channels: [0:256)=relu(f1), [256:512)=corr1, [512:768)=relu(f2), [768:1024)=corr2
// conv1: 1024->1024 3x3 SAME, conv2: 1024->512 3x3 SAME
// cls: 512 -> 512 (=2*256) 1x1, psroi-diag, avgpool(16x16), softmax(2)
// output: cls_prob(512) | corr1(16777216) | corr2(16777216), fp32

#define NB        256
#define HW        256
#define CH        256
#define OFF_C1    512
#define OFF_C2    (512 + 16777216)

// ---------------- device scratch (static: no allocs allowed) ----------------
__device__ __nv_bfloat16 g_XIN[(size_t)NB * 1024 * HW];   // conv1 input (concat), bf16
__device__ __nv_bfloat16 g_Y1 [(size_t)NB * 1024 * HW];   // conv1 output
__device__ __nv_bfloat16 g_Y2 [(size_t)NB *  512 * HW];   // conv2 output
__device__ float         g_invn1[NB * HW];
__device__ float         g_invn2[NB * HW];
__device__ __nv_bfloat16 g_W1[(size_t)8 * 64 * 9 * 128 * 16]; // conv1 w, swizzled bf16
__device__ __nv_bfloat16 g_W2[(size_t)4 * 64 * 9 * 128 * 16]; // conv2 w
__device__ float         g_wclsT[512 * 512];                  // cls w, transposed [ic][o]

// ---------------- K0: relu + channel-norms + bf16 copies ----------------
__global__ void k_norm(const float* __restrict__ f1, const float* __restrict__ f2,
                       __nv_bfloat16* __restrict__ xin,
                       float* __restrict__ invn1, float* __restrict__ invn2) {
    int b = blockIdx.x, p = threadIdx.x;
    const float* f1b = f1 + (size_t)b * 65536;
    const float* f2b = f2 + (size_t)b * 65536;
    __nv_bfloat16* xb = xin + (size_t)b * 262144;
    float s1 = 0.f, s2 = 0.f;
    #pragma unroll 4
    for (int c = 0; c < CH; ++c) {
        float v1 = fmaxf(f1b[c * HW + p], 0.f);
        float v2 = fmaxf(f2b[c * HW + p], 0.f);
        s1 += v1 * v1;  s2 += v2 * v2;
        xb[c * HW + p]         = __float2bfloat16(v1);
        xb[(512 + c) * HW + p] = __float2bfloat16(v2);
    }
    invn1[b * HW + p] = 1.0f / fmaxf(sqrtf(s1), 1e-12f);
    invn2[b * HW + p] = 1.0f / fmaxf(sqrtf(s2), 1e-12f);
}

// ---------------- weight prep ----------------
// out[(((ocb*64+cc)*9+tp)*128+oo)*16+ii] = w[(ocb*128+oo)*9216 + (cc*16+ii)*9 + tp]
__global__ void k_prepw(const float* __restrict__ w, __nv_bfloat16* __restrict__ o, int total) {
    int idx = blockIdx.x * blockDim.x + threadIdx.x;
    if (idx >= total) return;
    int ii = idx & 15;  int r = idx >> 4;
    int oo = r & 127;   r >>= 7;
    int tp = r % 9;     r /= 9;
    int cc = r & 63;    int ocb = r >> 6;
    int oc = ocb * 128 + oo;
    int ic = cc * 16 + ii;
    o[idx] = __float2bfloat16(w[(size_t)oc * 9216 + (size_t)ic * 9 + tp]);
}

__global__ void k_prepcls(const float* __restrict__ w, float* __restrict__ o) {
    int idx = blockIdx.x * blockDim.x + threadIdx.x;  // idx = ic*512 + oc
    if (idx >= 512 * 512) return;
    int ic = idx >> 9, oc = idx & 511;
    o[idx] = w[oc * 512 + ic];
}

// ---------------- K1: correlation GEMM (fp32), writes corr1+corr2 + bf16 copies ----------------
// corr1[b][k][p] = (sum_c relu(f2)[c][k] * relu(f1)[c][p]) * invn2[k] * invn1[p]
__global__ void __launch_bounds__(256) k_corr(
        const float* __restrict__ f1, const float* __restrict__ f2,
        float* __restrict__ out,
        const float* __restrict__ invn1, const float* __restrict__ invn2,
        __nv_bfloat16* __restrict__ xin) {
    __shared__ float A_s[16][132];
    __shared__ float B_s[16][132];
    int b = blockIdx.x, q = blockIdx.y;
    int kb = (q >> 1) * 128, pb = (q & 1) * 128;
    int t = threadIdx.x, tx = t & 15, ty = t >> 4;
    const float* f1b = f1 + (size_t)b * 65536;
    const float* f2b = f2 + (size_t)b * 65536;

    float acc[8][8];
    #pragma unroll
    for (int i = 0; i < 8; ++i)
        #pragma unroll
        for (int j = 0; j < 8; ++j) acc[i][j] = 0.f;

    for (int cc = 0; cc < 16; ++cc) {
        #pragma unroll
        for (int u = 0; u < 8; ++u) {
            int e = t + 256 * u;
            int c = e >> 7, k = e & 127;
            A_s[c][k] = fmaxf(f2b[(cc * 16 + c) * HW + kb + k], 0.f);
            B_s[c][k] = fmaxf(f1b[(cc * 16 + c) * HW + pb + k], 0.f);
        }
        __syncthreads();
        #pragma unroll
        for (int c = 0; c < 16; ++c) {
            float4 a0 = *(const float4*)&A_s[c][ty * 8];
            float4 a1 = *(const float4*)&A_s[c][ty * 8 + 4];
            float4 b0 = *(const float4*)&B_s[c][tx * 8];
            float4 b1 = *(const float4*)&B_s[c][tx * 8 + 4];
            float av[8] = {a0.x, a0.y, a0.z, a0.w, a1.x, a1.y, a1.z, a1.w};
            float bv[8] = {b0.x, b0.y, b0.z, b0.w, b1.x, b1.y, b1.z, b1.w};
            #pragma unroll
            for (int i = 0; i < 8; ++i)
                #pragma unroll
                for (int j = 0; j < 8; ++j) acc[i][j] += av[i] * bv[j];
        }
        __syncthreads();
    }

    float ik[8], ip[8];
    #pragma unroll
    for (int i = 0; i < 8; ++i) ik[i] = invn2[b * HW + kb + ty * 8 + i];
    #pragma unroll
    for (int j = 0; j < 8; ++j) ip[j] = invn1[b * HW + pb + tx * 8 + j];

    float* c1 = out + OFF_C1 + (size_t)b * 65536;
    float* c2 = out + OFF_C2 + (size_t)b * 65536;
    __nv_bfloat16* xb = xin + (size_t)b * 262144;

    #pragma unroll
    for (int i = 0; i < 8; ++i) {
        int k = kb + ty * 8 + i;
        #pragma unroll
        for (int j = 0; j < 8; ++j) {
            int p = pb + tx * 8 + j;
            float v = acc[i][j] * ik[i] * ip[j];
            c1[k * HW + p] = v;
            c2[p * HW + k] = v;
            __nv_bfloat16 vb = __float2bfloat16(v);
            xb[(256 + k) * HW + p] = vb;   // corr1 channels
            xb[(768 + p) * HW + k] = vb;   // corr2 channels (transposed)
        }
    }
}

// ---------------- conv 3x3 implicit GEMM (bf16 mma.sync, fp32 accum) ----------------
__device__ __forceinline__ void mma16816(float* c, const uint32_t* a, uint32_t b0, uint32_t b1) {
    asm volatile(
        "mma.sync.aligned.m16n8k16.row.col.f32.bf16.bf16.f32 "
        "{%0,%1,%2,%3}, {%4,%5,%6,%7}, {%8,%9}, {%0,%1,%2,%3};\n"
        : "+f"(c[0]), "+f"(c[1]), "+f"(c[2]), "+f"(c[3])
        : "r"(a[0]), "r"(a[1]), "r"(a[2]), "r"(a[3]), "r"(b0), "r"(b1));
}

// grid = (256 batches, OC/128). block = 512 threads (16 warps, 4M x 4N).
// block tile: M=128 oc, N=256 pixels (full image), K = 1024 ic x 9 taps.
__global__ void __launch_bounds__(512, 1) k_conv(
        const __nv_bfloat16* __restrict__ Xin,   // [b][1024][256]
        const __nv_bfloat16* __restrict__ Wg,    // [ocb][cc][tap][128][16]
        const float* __restrict__ bias,
        __nv_bfloat16* __restrict__ Yout,        // [b][OC][256]
        int OC) {
    __shared__ __align__(16) __nv_bfloat16 X_s[256][18];       // [pixel][ic16] (+pad)
    __shared__ __align__(16) __nv_bfloat16 W_s[9][128][16];    // [tap][oc][ic16]

    int b = blockIdx.x, ocb = blockIdx.y;
    int t = threadIdx.x;
    int lane = t & 31, wid = t >> 5;
    int g = lane >> 2, tg = lane & 3;
    int wm = (wid & 3) * 32;    // warp oc base within block
    int wn = (wid >> 2) * 64;   // warp pixel base

    const __nv_bfloat16* xb = Xin + (size_t)b * 262144;
    const __nv_bfloat16* wb = Wg + (size_t)ocb * (64 * 9 * 2048);

    float acc[2][8][4];
    #pragma unroll
    for (int mi = 0; mi < 2; ++mi)
        #pragma unroll
        for (int j = 0; j < 8; ++j)
            #pragma unroll
            for (int r = 0; r < 4; ++r) acc[mi][j][r] = 0.f;

    int yj[8], xjj[8];
    #pragma unroll
    for (int j = 0; j < 8; ++j) {
        int p = wn + j * 8 + g;
        yj[j] = p >> 4; xjj[j] = p & 15;
    }

    for (int cc = 0; cc < 64; ++cc) {
        // stage input chunk [16 ic][256 px] -> X_s[px][ic]
        #pragma unroll
        for (int u = 0; u < 8; ++u) {
            int e = t + 512 * u;
            int i = e >> 8, p = e & 255;
            X_s[p][i] = xb[(cc * 16 + i) * HW + p];
        }
        // stage weights [9][128][16] (contiguous in global)
        {
            const uint2* wsrc = (const uint2*)(wb + (size_t)cc * (9 * 2048));
            uint2* wdst = (uint2*)(&W_s[0][0][0]);
            #pragma unroll
            for (int u = 0; u < 9; ++u) {
                int v = t + 512 * u;
                if (v < 4608) wdst[v] = wsrc[v];
            }
        }
        __syncthreads();

        #pragma unroll
        for (int tap = 0; tap < 9; ++tap) {
            const int dy = tap / 3 - 1, dx = tap % 3 - 1;
            uint32_t a[2][4];
            #pragma unroll
            for (int mi = 0; mi < 2; ++mi) {
                const __nv_bfloat16* wr = &W_s[tap][wm + mi * 16 + g][0];
                a[mi][0] = *(const uint32_t*)(wr + 2 * tg);
                a[mi][1] = *(const uint32_t*)(wr + 128 + 2 * tg);       // +8 rows * 16
                a[mi][2] = *(const uint32_t*)(wr + 2 * tg + 8);
                a[mi][3] = *(const uint32_t*)(wr + 128 + 2 * tg + 8);
            }
            #pragma unroll
            for (int j = 0; j < 8; ++j) {
                int yy = yj[j] + dy, xx = xjj[j] + dx;
                uint32_t b0 = 0u, b1 = 0u;
                if ((unsigned)yy < 16u && (unsigned)xx < 16u) {
                    const __nv_bfloat16* xr = &X_s[yy * 16 + xx][0];
                    b0 = *(const uint32_t*)(xr + 2 * tg);
                    b1 = *(const uint32_t*)(xr + 2 * tg + 8);
                }
                mma16816(acc[0][j], a[0], b0, b1);
                mma16816(acc[1][j], a[1], b0, b1);
            }
        }
        __syncthreads();
    }

    // epilogue: +bias, relu, bf16 store
    __nv_bfloat16* yb = Yout + (size_t)b * OC * HW;
    #pragma unroll
    for (int mi = 0; mi < 2; ++mi) {
        int oc0 = ocb * 128 + wm + mi * 16 + g;
        int oc1 = oc0 + 8;
        float bz0 = bias[oc0], bz1 = bias[oc1];
        #pragma unroll
        for (int j = 0; j < 8; ++j) {
            int p0 = wn + j * 8 + 2 * tg;
            const float* ac = acc[mi][j];
            __nv_bfloat162 v0, v1;
            v0.x = __float2bfloat16(fmaxf(ac[0] + bz0, 0.f));
            v0.y = __float2bfloat16(fmaxf(ac[1] + bz0, 0.f));
            v1.x = __float2bfloat16(fmaxf(ac[2] + bz1, 0.f));
            v1.y = __float2bfloat16(fmaxf(ac[3] + bz1, 0.f));
            *(__nv_bfloat162*)(&yb[(size_t)oc0 * HW + p0]) = v0;
            *(__nv_bfloat162*)(&yb[(size_t)oc1 * HW + p0]) = v1;
        }
    }
}

// ---------------- final head: 1x1 conv (diag only) + avgpool + softmax ----------------
__global__ void k_final(const __nv_bfloat16* __restrict__ Y2,
                        const float* __restrict__ wT,     // [ic][o], o = c*256+p
                        float* __restrict__ out) {
    int b = blockIdx.x, p = threadIdx.x;
    const __nv_bfloat16* yb = Y2 + (size_t)b * 131072;
    float a0 = 0.f, a1 = 0.f;
    #pragma unroll 8
    for (int ic = 0; ic < 512; ++ic) {
        float y = __bfloat162float(yb[ic * HW + p]);
        a0 += wT[ic * 512 + p] * y;
        a1 += wT[ic * 512 + 256 + p] * y;
    }
    a0 = fmaxf(a0, 0.f);
    a1 = fmaxf(a1, 0.f);
    __shared__ float s0[256], s1[256];
    s0[p] = a0; s1[p] = a1;
    __syncthreads();
    for (int st = 128; st > 0; st >>= 1) {
        if (p < st) { s0[p] += s0[p + st]; s1[p] += s1[p + st]; }
        __syncthreads();
    }
    if (p == 0) {
        float m0 = s0[0] * (1.0f / 256.0f);
        float m1 = s1[0] * (1.0f / 256.0f);
        float mx = fmaxf(m0, m1);
        float e0 = expf(m0 - mx), e1 = expf(m1 - mx);
        float inv = 1.0f / (e0 + e1);
        out[b * 2 + 0] = e0 * inv;
        out[b * 2 + 1] = e1 * inv;
    }
}

// ---------------- launch ----------------
extern "C" void kernel_launch(void* const* d_in, const int* in_sizes, int n_in,
                              void* d_out, int out_size) {
    const float* f1      = (const float*)d_in[0];
    const float* f2      = (const float*)d_in[1];
    const float* conv1_w = (const float*)d_in[2];
    const float* conv1_b = (const float*)d_in[3];
    const float* conv2_w = (const float*)d_in[4];
    const float* conv2_b = (const float*)d_in[5];
    const float* cls_w   = (const float*)d_in[6];
    float* out = (float*)d_out;

    __nv_bfloat16 *xin, *y1, *y2, *w1, *w2;
    float *invn1, *invn2, *wclsT;
    cudaGetSymbolAddress((void**)&xin,   g_XIN);
    cudaGetSymbolAddress((void**)&y1,    g_Y1);
    cudaGetSymbolAddress((void**)&y2,    g_Y2);
    cudaGetSymbolAddress((void**)&w1,    g_W1);
    cudaGetSymbolAddress((void**)&w2,    g_W2);
    cudaGetSymbolAddress((void**)&invn1, g_invn1);
    cudaGetSymbolAddress((void**)&invn2, g_invn2);
    cudaGetSymbolAddress((void**)&wclsT, g_wclsT);

    // prep
    k_norm<<<NB, 256>>>(f1, f2, xin, invn1, invn2);
    {
        int tot1 = 8 * 64 * 9 * 2048;  // 9,437,184
        k_prepw<<<(tot1 + 255) / 256, 256>>>(conv1_w, w1, tot1);
        int tot2 = 4 * 64 * 9 * 2048;  // 4,718,592
        k_prepw<<<(tot2 + 255) / 256, 256>>>(conv2_w, w2, tot2);
        k_prepcls<<<(512 * 512 + 255) / 256, 256>>>(cls_w, wclsT);
    }
    // correlation (writes corr1 + corr2 to d_out, bf16 copies into xin)
    k_corr<<<dim3(NB, 4), 256>>>(f1, f2, out, invn1, invn2, xin);
    // convs
    k_conv<<<dim3(NB, 8), 512>>>(xin, w1, conv1_b, y1, 1024);
    k_conv<<<dim3(NB, 4), 512>>>(y1,  w2, conv2_b, y2, 512);
    // head
    k_final<<<NB, 256>>>(y2, wclsT, out);
}

// round 4
// speedup vs baseline: 1.0043x; 1.0043x over previous
#include <cuda_runtime.h>
#include <cuda_bf16.h>
#include <cstdint>

// ---------------- problem constants ----------------
// BS=256, C=256, H=W=16, HW=256
// feat channels: [0:256)=relu(f1), [256:512)=corr1, [512:768)=relu(f2), [768:1024)=corr2
// conv1: 1024->1024 3x3 SAME, conv2: 1024->512 3x3 SAME
// cls: 512 -> 512 (=2*256) 1x1, psroi-diag, avgpool(16x16), softmax(2)
// output: cls_prob(512) | corr1(16777216) | corr2(16777216), fp32

#define NB        256
#define HW        256
#define CH        256
#define OFF_C1    512
#define OFF_C2    (512 + 16777216)

// ---------------- device scratch (static: no allocs allowed) ----------------
__device__ __nv_bfloat16 g_XIN[(size_t)NB * 1024 * HW];   // conv1 input (concat), bf16
__device__ __nv_bfloat16 g_Y1 [(size_t)NB * 1024 * HW];   // conv1 output
__device__ __nv_bfloat16 g_Y2 [(size_t)NB *  512 * HW];   // conv2 output
__device__ float         g_invn1[NB * HW];
__device__ float         g_invn2[NB * HW];
__device__ __nv_bfloat16 g_W1[(size_t)8 * 64 * 9 * 128 * 16]; // conv1 w, swizzled bf16
__device__ __nv_bfloat16 g_W2[(size_t)4 * 64 * 9 * 128 * 16]; // conv2 w
__device__ float         g_wclsT[512 * 512];                  // cls w, transposed [ic][o]

// ---------------- K0: relu + channel-norms + bf16 copies ----------------
__global__ void k_norm(const float* __restrict__ f1, const float* __restrict__ f2,
                       __nv_bfloat16* __restrict__ xin,
                       float* __restrict__ invn1, float* __restrict__ invn2) {
    int b = blockIdx.x, p = threadIdx.x;
    const float* f1b = f1 + (size_t)b * 65536;
    const float* f2b = f2 + (size_t)b * 65536;
    __nv_bfloat16* xb = xin + (size_t)b * 262144;
    float s1 = 0.f, s2 = 0.f;
    #pragma unroll 4
    for (int c = 0; c < CH; ++c) {
        float v1 = fmaxf(f1b[c * HW + p], 0.f);
        float v2 = fmaxf(f2b[c * HW + p], 0.f);
        s1 += v1 * v1;  s2 += v2 * v2;
        xb[c * HW + p]         = __float2bfloat16(v1);
        xb[(512 + c) * HW + p] = __float2bfloat16(v2);
    }
    invn1[b * HW + p] = 1.0f / fmaxf(sqrtf(s1), 1e-12f);
    invn2[b * HW + p] = 1.0f / fmaxf(sqrtf(s2), 1e-12f);
}

// ---------------- weight prep ----------------
// out[(((ocb*64+cc)*9+tp)*128+oo)*16+ii] = w[(ocb*128+oo)*9216 + (cc*16+ii)*9 + tp]
__global__ void k_prepw(const float* __restrict__ w, __nv_bfloat16* __restrict__ o, int total) {
    int idx = blockIdx.x * blockDim.x + threadIdx.x;
    if (idx >= total) return;
    int ii = idx & 15;  int r = idx >> 4;
    int oo = r & 127;   r >>= 7;
    int tp = r % 9;     r /= 9;
    int cc = r & 63;    int ocb = r >> 6;
    int oc = ocb * 128 + oo;
    int ic = cc * 16 + ii;
    o[idx] = __float2bfloat16(w[(size_t)oc * 9216 + (size_t)ic * 9 + tp]);
}

__global__ void k_prepcls(const float* __restrict__ w, float* __restrict__ o) {
    int idx = blockIdx.x * blockDim.x + threadIdx.x;  // idx = ic*512 + oc
    if (idx >= 512 * 512) return;
    int ic = idx >> 9, oc = idx & 511;
    o[idx] = w[oc * 512 + ic];
}

// ---------------- K1: correlation GEMM (fp32), writes corr1+corr2 + bf16 copies ----------------
// corr1[b][k][p] = (sum_c relu(f2)[c][k] * relu(f1)[c][p]) * invn2[k] * invn1[p]
__global__ void __launch_bounds__(256) k_corr(
        const float* __restrict__ f1, const float* __restrict__ f2,
        float* __restrict__ out,
        const float* __restrict__ invn1, const float* __restrict__ invn2,
        __nv_bfloat16* __restrict__ xin) {
    __shared__ float A_s[16][132];
    __shared__ float B_s[16][132];
    int b = blockIdx.x, q = blockIdx.y;
    int kb = (q >> 1) * 128, pb = (q & 1) * 128;
    int t = threadIdx.x, tx = t & 15, ty = t >> 4;
    const float* f1b = f1 + (size_t)b * 65536;
    const float* f2b = f2 + (size_t)b * 65536;

    float acc[8][8];
    #pragma unroll
    for (int i = 0; i < 8; ++i)
        #pragma unroll
        for (int j = 0; j < 8; ++j) acc[i][j] = 0.f;

    for (int cc = 0; cc < 16; ++cc) {
        #pragma unroll
        for (int u = 0; u < 8; ++u) {
            int e = t + 256 * u;
            int c = e >> 7, k = e & 127;
            A_s[c][k] = fmaxf(f2b[(cc * 16 + c) * HW + kb + k], 0.f);
            B_s[c][k] = fmaxf(f1b[(cc * 16 + c) * HW + pb + k], 0.f);
        }
        __syncthreads();
        #pragma unroll
        for (int c = 0; c < 16; ++c) {
            float4 a0 = *(const float4*)&A_s[c][ty * 8];
            float4 a1 = *(const float4*)&A_s[c][ty * 8 + 4];
            float4 b0 = *(const float4*)&B_s[c][tx * 8];
            float4 b1 = *(const float4*)&B_s[c][tx * 8 + 4];
            float av[8] = {a0.x, a0.y, a0.z, a0.w, a1.x, a1.y, a1.z, a1.w};
            float bv[8] = {b0.x, b0.y, b0.z, b0.w, b1.x, b1.y, b1.z, b1.w};
            #pragma unroll
            for (int i = 0; i < 8; ++i)
                #pragma unroll
                for (int j = 0; j < 8; ++j) acc[i][j] += av[i] * bv[j];
        }
        __syncthreads();
    }

    float ik[8], ip[8];
    #pragma unroll
    for (int i = 0; i < 8; ++i) ik[i] = invn2[b * HW + kb + ty * 8 + i];
    #pragma unroll
    for (int j = 0; j < 8; ++j) ip[j] = invn1[b * HW + pb + tx * 8 + j];

    float* c1 = out + OFF_C1 + (size_t)b * 65536;
    float* c2 = out + OFF_C2 + (size_t)b * 65536;
    __nv_bfloat16* xb = xin + (size_t)b * 262144;

    #pragma unroll
    for (int i = 0; i < 8; ++i) {
        int k = kb + ty * 8 + i;
        #pragma unroll
        for (int j = 0; j < 8; ++j) {
            int p = pb + tx * 8 + j;
            float v = acc[i][j] * ik[i] * ip[j];
            c1[k * HW + p] = v;
            c2[p * HW + k] = v;
            __nv_bfloat16 vb = __float2bfloat16(v);
            xb[(256 + k) * HW + p] = vb;   // corr1 channels
            xb[(768 + p) * HW + k] = vb;   // corr2 channels (transposed)
        }
    }
}

// ---------------- conv 3x3 implicit GEMM (bf16 mma.sync, fp32 accum) ----------------
__device__ __forceinline__ void mma16816(float* c, const uint32_t* a, uint32_t b0, uint32_t b1) {
    asm volatile(
        "mma.sync.aligned.m16n8k16.row.col.f32.bf16.bf16.f32 "
        "{%0,%1,%2,%3}, {%4,%5,%6,%7}, {%8,%9}, {%0,%1,%2,%3};\n"
        : "+f"(c[0]), "+f"(c[1]), "+f"(c[2]), "+f"(c[3])
        : "r"(a[0]), "r"(a[1]), "r"(a[2]), "r"(a[3]), "r"(b0), "r"(b1));
}

// grid = (256 batches, OC/128). block = 512 threads (16 warps, 4M x 4N).
// block tile: M=128 oc, N=256 pixels (full image), K = 1024 ic x 9 taps.
__global__ void __launch_bounds__(512, 1) k_conv(
        const __nv_bfloat16* __restrict__ Xin,   // [b][1024][256]
        const __nv_bfloat16* __restrict__ Wg,    // [ocb][cc][tap][128][16]
        const float* __restrict__ bias,
        __nv_bfloat16* __restrict__ Yout,        // [b][OC][256]
        int OC) {
    __shared__ __align__(16) __nv_bfloat16 X_s[256][18];       // [pixel][ic16] (+pad)
    __shared__ __align__(16) __nv_bfloat16 W_s[9][128][16];    // [tap][oc][ic16]

    int b = blockIdx.x, ocb = blockIdx.y;
    int t = threadIdx.x;
    int lane = t & 31, wid = t >> 5;
    int g = lane >> 2, tg = lane & 3;
    int wm = (wid & 3) * 32;    // warp oc base within block
    int wn = (wid >> 2) * 64;   // warp pixel base

    const __nv_bfloat16* xb = Xin + (size_t)b * 262144;
    const __nv_bfloat16* wb = Wg + (size_t)ocb * (64 * 9 * 2048);

    float acc[2][8][4];
    #pragma unroll
    for (int mi = 0; mi < 2; ++mi)
        #pragma unroll
        for (int j = 0; j < 8; ++j)
            #pragma unroll
            for (int r = 0; r < 4; ++r) acc[mi][j][r] = 0.f;

    int yj[8], xjj[8];
    #pragma unroll
    for (int j = 0; j < 8; ++j) {
        int p = wn + j * 8 + g;
        yj[j] = p >> 4; xjj[j] = p & 15;
    }

    for (int cc = 0; cc < 64; ++cc) {
        // stage input chunk [16 ic][256 px] -> X_s[px][ic]
        #pragma unroll
        for (int u = 0; u < 8; ++u) {
            int e = t + 512 * u;
            int i = e >> 8, p = e & 255;
            X_s[p][i] = xb[(cc * 16 + i) * HW + p];
        }
        // stage weights [9][128][16] (contiguous in global)
        {
            const uint2* wsrc = (const uint2*)(wb + (size_t)cc * (9 * 2048));
            uint2* wdst = (uint2*)(&W_s[0][0][0]);
            #pragma unroll
            for (int u = 0; u < 9; ++u) {
                int v = t + 512 * u;
                if (v < 4608) wdst[v] = wsrc[v];
            }
        }
        __syncthreads();

        #pragma unroll
        for (int tap = 0; tap < 9; ++tap) {
            const int dy = tap / 3 - 1, dx = tap % 3 - 1;
            uint32_t a[2][4];
            #pragma unroll
            for (int mi = 0; mi < 2; ++mi) {
                const __nv_bfloat16* wr = &W_s[tap][wm + mi * 16 + g][0];
                a[mi][0] = *(const uint32_t*)(wr + 2 * tg);
                a[mi][1] = *(const uint32_t*)(wr + 128 + 2 * tg);       // +8 rows * 16
                a[mi][2] = *(const uint32_t*)(wr + 2 * tg + 8);
                a[mi][3] = *(const uint32_t*)(wr + 128 + 2 * tg + 8);
            }
            #pragma unroll
            for (int j = 0; j < 8; ++j) {
                int yy = yj[j] + dy, xx = xjj[j] + dx;
                uint32_t b0 = 0u, b1 = 0u;
                if ((unsigned)yy < 16u && (unsigned)xx < 16u) {
                    const __nv_bfloat16* xr = &X_s[yy * 16 + xx][0];
                    b0 = *(const uint32_t*)(xr + 2 * tg);
                    b1 = *(const uint32_t*)(xr + 2 * tg + 8);
                }
                mma16816(acc[0][j], a[0], b0, b1);
                mma16816(acc[1][j], a[1], b0, b1);
            }
        }
        __syncthreads();
    }

    // epilogue: +bias, relu, bf16 store
    __nv_bfloat16* yb = Yout + (size_t)b * OC * HW;
    #pragma unroll
    for (int mi = 0; mi < 2; ++mi) {
        int oc0 = ocb * 128 + wm + mi * 16 + g;
        int oc1 = oc0 + 8;
        float bz0 = bias[oc0], bz1 = bias[oc1];
        #pragma unroll
        for (int j = 0; j < 8; ++j) {
            int p0 = wn + j * 8 + 2 * tg;
            const float* ac = acc[mi][j];
            __nv_bfloat162 v0, v1;
            v0.x = __float2bfloat16(fmaxf(ac[0] + bz0, 0.f));
            v0.y = __float2bfloat16(fmaxf(ac[1] + bz0, 0.f));
            v1.x = __float2bfloat16(fmaxf(ac[2] + bz1, 0.f));
            v1.y = __float2bfloat16(fmaxf(ac[3] + bz1, 0.f));
            *(__nv_bfloat162*)(&yb[(size_t)oc0 * HW + p0]) = v0;
            *(__nv_bfloat162*)(&yb[(size_t)oc1 * HW + p0]) = v1;
        }
    }
}

// ---------------- final head: 1x1 conv (diag only) + avgpool + softmax ----------------
__global__ void k_final(const __nv_bfloat16* __restrict__ Y2,
                        const float* __restrict__ wT,     // [ic][o], o = c*256+p
                        float* __restrict__ out) {
    int b = blockIdx.x, p = threadIdx.x;
    const __nv_bfloat16* yb = Y2 + (size_t)b * 131072;
    float a0 = 0.f, a1 = 0.f;
    #pragma unroll 8
    for (int ic = 0; ic < 512; ++ic) {
        float y = __bfloat162float(yb[ic * HW + p]);
        a0 += wT[ic * 512 + p] * y;
        a1 += wT[ic * 512 + 256 + p] * y;
    }
    a0 = fmaxf(a0, 0.f);
    a1 = fmaxf(a1, 0.f);
    __shared__ float s0[256], s1[256];
    s0[p] = a0; s1[p] = a1;
    __syncthreads();
    for (int st = 128; st > 0; st >>= 1) {
        if (p < st) { s0[p] += s0[p + st]; s1[p] += s1[p + st]; }
        __syncthreads();
    }
    if (p == 0) {
        float m0 = s0[0] * (1.0f / 256.0f);
        float m1 = s1[0] * (1.0f / 256.0f);
        float mx = fmaxf(m0, m1);
        float e0 = expf(m0 - mx), e1 = expf(m1 - mx);
        float inv = 1.0f / (e0 + e1);
        out[b * 2 + 0] = e0 * inv;
        out[b * 2 + 1] = e1 * inv;
    }
}

// ---------------- launch ----------------
extern "C" void kernel_launch(void* const* d_in, const int* in_sizes, int n_in,
                              void* d_out, int out_size) {
    const float* f1      = (const float*)d_in[0];
    const float* f2      = (const float*)d_in[1];
    const float* conv1_w = (const float*)d_in[2];
    const float* conv1_b = (const float*)d_in[3];
    const float* conv2_w = (const float*)d_in[4];
    const float* conv2_b = (const float*)d_in[5];
    const float* cls_w   = (const float*)d_in[6];
    float* out = (float*)d_out;

    __nv_bfloat16 *xin, *y1, *y2, *w1, *w2;
    float *invn1, *invn2, *wclsT;
    cudaGetSymbolAddress((void**)&xin,   g_XIN);
    cudaGetSymbolAddress((void**)&y1,    g_Y1);
    cudaGetSymbolAddress((void**)&y2,    g_Y2);
    cudaGetSymbolAddress((void**)&w1,    g_W1);
    cudaGetSymbolAddress((void**)&w2,    g_W2);
    cudaGetSymbolAddress((void**)&invn1, g_invn1);
    cudaGetSymbolAddress((void**)&invn2, g_invn2);
    cudaGetSymbolAddress((void**)&wclsT, g_wclsT);

    // prep
    k_norm<<<NB, 256>>>(f1, f2, xin, invn1, invn2);
    {
        int tot1 = 8 * 64 * 9 * 2048;  // 9,437,184
        k_prepw<<<(tot1 + 255) / 256, 256>>>(conv1_w, w1, tot1);
        int tot2 = 4 * 64 * 9 * 2048;  // 4,718,592
        k_prepw<<<(tot2 + 255) / 256, 256>>>(conv2_w, w2, tot2);
        k_prepcls<<<(512 * 512 + 255) / 256, 256>>>(cls_w, wclsT);
    }
    // correlation (writes corr1 + corr2 to d_out, bf16 copies into xin)
    k_corr<<<dim3(NB, 4), 256>>>(f1, f2, out, invn1, invn2, xin);
    // convs
    k_conv<<<dim3(NB, 8), 512>>>(xin, w1, conv1_b, y1, 1024);
    k_conv<<<dim3(NB, 4), 512>>>(y1,  w2, conv2_b, y2, 512);
    // head
    k_final<<<NB, 256>>>(y2, wclsT, out);
}